// round 2
// baseline (speedup 1.0000x reference)
#include <cuda_runtime.h>

#define NN 207
#define EE 1722
#define TT 24
#define BB 64
#define LL 2048
#define RESV 12
#define L4 (LL / 4)      // 512 float4 per row
#define LT4 32           // float4 per L-tile (= 128 floats)
#define NTHREADS 256

// ---------------- device scratch (no allocation allowed) ----------------
struct __align__(16) EF { float wr; float wra; int noff; int pad; };
struct __align__(8)  ET { float wdc; int noff; };

__device__ EF     g_ef[TT * EE];      // from-CSR ordered, per t (reaction gathers)
__device__ ET     g_et[TT * EE];      // to-CSR ordered, per t (diffusion gathers)
__device__ float4 g_c1[TT * NN];      // (cd_r, cd_ra, cd_d+cd_da+1, br)
__device__ float2 g_c2[TT * NN];      // (bra, bd+bda)
__device__ int    g_from_off[NN + 1];
__device__ int    g_to_off[NN + 1];
__device__ int    g_from_idx[EE];
__device__ int    g_to_idx[EE];
__device__ int    g_fnoff[EE];        // edge_to * LT4 for from-CSR
__device__ int    g_tnoff[EE];        // edge_from * LT4 for to-CSR

// ---------------- prepass 1: deterministic CSR build ----------------
__global__ void rd_build_csr(const int* __restrict__ ef, const int* __restrict__ et) {
    __shared__ int sf[EE], st[EE];
    __shared__ int cF[NN], cT[NN];
    __shared__ int oF[NN + 1], oT[NN + 1];
    int tid = threadIdx.x;

    for (int i = tid; i < EE; i += blockDim.x) { sf[i] = ef[i]; st[i] = et[i]; }
    for (int i = tid; i < NN; i += blockDim.x) { cF[i] = 0; cT[i] = 0; }
    __syncthreads();

    for (int i = tid; i < EE; i += blockDim.x) {
        atomicAdd(&cF[sf[i]], 1);
        atomicAdd(&cT[st[i]], 1);
    }
    __syncthreads();

    if (tid == 0) {
        int a = 0, b = 0;
        for (int w = 0; w < NN; w++) { oF[w] = a; a += cF[w]; oT[w] = b; b += cT[w]; }
        oF[NN] = a; oT[NN] = b;
    }
    __syncthreads();

    for (int i = tid; i <= NN; i += blockDim.x) { g_from_off[i] = oF[i]; g_to_off[i] = oT[i]; }
    for (int i = tid; i < NN; i += blockDim.x) { cF[i] = 0; cT[i] = 0; }
    __syncthreads();

    // atomic placement (order nondeterministic) ...
    for (int i = tid; i < EE; i += blockDim.x) {
        int f = sf[i]; int p = oF[f] + atomicAdd(&cF[f], 1); g_from_idx[p] = i;
        int t2 = st[i]; int q = oT[t2] + atomicAdd(&cT[t2], 1); g_to_idx[q] = i;
    }
    __syncthreads();

    // ... then per-bucket insertion sort by edge id => fully deterministic CSR
    if (tid < NN) {
        {
            int a = oF[tid], b2 = oF[tid + 1];
            for (int i = a + 1; i < b2; i++) {
                int v = g_from_idx[i]; int j = i - 1;
                while (j >= a && g_from_idx[j] > v) { g_from_idx[j + 1] = g_from_idx[j]; j--; }
                g_from_idx[j + 1] = v;
            }
            for (int i = a; i < b2; i++) g_fnoff[i] = st[g_from_idx[i]] * LT4;
        }
        {
            int a = oT[tid], b2 = oT[tid + 1];
            for (int i = a + 1; i < b2; i++) {
                int v = g_to_idx[i]; int j = i - 1;
                while (j >= a && g_to_idx[j] > v) { g_to_idx[j + 1] = g_to_idx[j]; j--; }
                g_to_idx[j + 1] = v;
            }
            for (int i = a; i < b2; i++) g_tnoff[i] = sf[g_to_idx[i]] * LT4;
        }
    }
}

// ---------------- prepass 2: per-t packed weights + diagonals ----------------
// Reference math (per batch with time slot t, per output row w):
//   reaction   = (Σ_{to=w} wr) x[w]  − Σ_{from=w} wr  x[to]  + br
//   reaction_a = (Σ_{to=w} wra) x[w] + Σ_{from=w} wra x[to]  + bra   (diag = 0 when b==0)
//   diffusion  = (Σ_{from=w} wd) x[w] − Σ_{to=w} wd  x[from] + bd
//   diffusion_a= (Σ_{from=w} wda) x[w] + Σ_{to=w} wda x[from]+ bda
// linear part combines: (Σwd + Σwda + 1) x[w] + Σ_{to=w}(wda−wd) x[from] + (bd+bda)
__global__ void rd_prep(const float* __restrict__ wr,  const float* __restrict__ wd,
                        const float* __restrict__ wra, const float* __restrict__ wda,
                        const float* __restrict__ br,  const float* __restrict__ bd,
                        const float* __restrict__ bra, const float* __restrict__ bda) {
    int t = blockIdx.x;
    int w = threadIdx.x;
    if (w >= NN) return;

    // from-CSR: pack reaction gather weights; accumulate DIFFUSION diagonals
    float dd = 0.f, dda = 0.f;
    int k0 = g_from_off[w], k1 = g_from_off[w + 1];
    for (int k = k0; k < k1; k++) {
        int e = g_from_idx[k];
        EF rec; rec.wr = wr[t * EE + e]; rec.wra = wra[t * EE + e];
        rec.noff = g_fnoff[k]; rec.pad = 0;
        g_ef[t * EE + k] = rec;
        dd  += wd[t * EE + e];
        dda += wda[t * EE + e];
    }

    // to-CSR: pack diffusion gather weight; accumulate REACTION diagonals
    float dr = 0.f, dra = 0.f;
    k0 = g_to_off[w]; k1 = g_to_off[w + 1];
    for (int k = k0; k < k1; k++) {
        int e = g_to_idx[k];
        ET rec; rec.wdc = wda[t * EE + e] - wd[t * EE + e]; rec.noff = g_tnoff[k];
        g_et[t * EE + k] = rec;
        dr  += wr[t * EE + e];
        dra += wra[t * EE + e];
    }

    float4 c1; c1.x = dr; c1.y = dra; c1.z = dd + dda + 1.f; c1.w = br[t * NN + w];
    g_c1[t * NN + w] = c1;
    float2 c2; c2.x = bra[t * NN + w]; c2.y = bd[t * NN + w] + bda[t * NN + w];
    g_c2[t * NN + w] = c2;
}

// ---------------- fast tanh: abs err ~1e-7 ----------------
__device__ __forceinline__ float ftanh(float x) {
    float xc = fminf(fmaxf(x, -15.f), 15.f);
    float e = __expf(xc + xc);
    return 1.f - __fdividef(2.f, e + 1.f);
}

// ---------------- main kernel ----------------
__global__ __launch_bounds__(NTHREADS, 2)
void rd_main(const float* __restrict__ X, const int* __restrict__ ind,
             float* __restrict__ out) {
    extern __shared__ float4 xs4[];   // [NN][LT4]
    const int b   = blockIdx.y;
    const int l0q = blockIdx.x * LT4;           // float4 column offset
    const int t   = ind[b] / RESV;
    const int tid = threadIdx.x;

    // load x tile: inputs[b, 0, :, l0:l0+128]  (channel 0 only)
    const float4* xb4 = reinterpret_cast<const float4*>(X)
                        + (size_t)b * 2 * NN * L4 + l0q;
    for (int idx = tid; idx < NN * LT4; idx += NTHREADS) {
        int w = idx >> 5, c = idx & (LT4 - 1);
        xs4[idx] = xb4[(size_t)w * L4 + c];
    }
    __syncthreads();

    const int lane = tid & 31;
    const int wg   = tid >> 5;
    const bool b0  = (b == 0);
    float4* ob4 = reinterpret_cast<float4*>(out) + (size_t)b * NN * L4 + l0q + lane;
    const EF* __restrict__ efp = g_ef + t * EE;
    const ET* __restrict__ etp = g_et + t * EE;

    for (int w = wg; w < NN; w += NTHREADS / 32) {
        float4 xw = xs4[w * LT4 + lane];
        float4 c1 = g_c1[t * NN + w];
        float2 c2 = g_c2[t * NN + w];
        float dra = b0 ? 0.f : c1.y;   // batch 0: RWa diag is exactly zero

        // r  = dr*x + br - Σ wr*x[to]
        // ra = dra*x + bra + Σ wra*x[to]
        // lin = (dd+dda+1)*x + (bd+bda) + Σ (wda-wd)*x[from]
        float4 r, ra, lin;
        r.x  = fmaf(c1.x, xw.x, c1.w);  r.y  = fmaf(c1.x, xw.y, c1.w);
        r.z  = fmaf(c1.x, xw.z, c1.w);  r.w  = fmaf(c1.x, xw.w, c1.w);
        ra.x = fmaf(dra,  xw.x, c2.x);  ra.y = fmaf(dra,  xw.y, c2.x);
        ra.z = fmaf(dra,  xw.z, c2.x);  ra.w = fmaf(dra,  xw.w, c2.x);
        lin.x = fmaf(c1.z, xw.x, c2.y); lin.y = fmaf(c1.z, xw.y, c2.y);
        lin.z = fmaf(c1.z, xw.z, c2.y); lin.w = fmaf(c1.z, xw.w, c2.y);

        int k0 = g_from_off[w], k1 = g_from_off[w + 1];
        for (int k = k0; k < k1; k++) {
            EF e = efp[k];
            float4 xv = xs4[e.noff + lane];
            r.x  = fmaf(-e.wr, xv.x, r.x);   r.y  = fmaf(-e.wr, xv.y, r.y);
            r.z  = fmaf(-e.wr, xv.z, r.z);   r.w  = fmaf(-e.wr, xv.w, r.w);
            ra.x = fmaf(e.wra, xv.x, ra.x);  ra.y = fmaf(e.wra, xv.y, ra.y);
            ra.z = fmaf(e.wra, xv.z, ra.z);  ra.w = fmaf(e.wra, xv.w, ra.w);
        }

        k0 = g_to_off[w]; k1 = g_to_off[w + 1];
        for (int k = k0; k < k1; k++) {
            ET e = etp[k];
            float4 xv = xs4[e.noff + lane];
            lin.x = fmaf(e.wdc, xv.x, lin.x); lin.y = fmaf(e.wdc, xv.y, lin.y);
            lin.z = fmaf(e.wdc, xv.z, lin.z); lin.w = fmaf(e.wdc, xv.w, lin.w);
        }

        float4 o;
        o.x = ftanh(r.x) + ftanh(ra.x) + lin.x;
        o.y = ftanh(r.y) + ftanh(ra.y) + lin.y;
        o.z = ftanh(r.z) + ftanh(ra.z) + lin.z;
        o.w = ftanh(r.w) + ftanh(ra.w) + lin.w;
        ob4[(size_t)w * L4] = o;
    }
}

// ---------------- launch ----------------
extern "C" void kernel_launch(void* const* d_in, const int* in_sizes, int n_in,
                              void* d_out, int out_size) {
    const float* X   = (const float*)d_in[0];
    const int*   ind = (const int*)d_in[1];
    const int*   ef  = (const int*)d_in[2];
    const int*   et  = (const int*)d_in[3];
    const float* wr  = (const float*)d_in[4];
    const float* wd  = (const float*)d_in[5];
    const float* wra = (const float*)d_in[6];
    const float* wda = (const float*)d_in[7];
    const float* br  = (const float*)d_in[8];
    const float* bd  = (const float*)d_in[9];
    const float* bra = (const float*)d_in[10];
    const float* bda = (const float*)d_in[11];
    float* out = (float*)d_out;

    const int smem = NN * LT4 * (int)sizeof(float4);   // 105,984 B
    cudaFuncSetAttribute(rd_main, cudaFuncAttributeMaxDynamicSharedMemorySize, smem);

    rd_build_csr<<<1, 256>>>(ef, et);
    rd_prep<<<TT, 256>>>(wr, wd, wra, wda, br, bd, bra, bda);

    dim3 grid(LL / (LT4 * 4), BB);   // (16, 64)
    rd_main<<<grid, NTHREADS, smem>>>(X, ind, out);
}